// round 1
// baseline (speedup 1.0000x reference)
#include <cuda_runtime.h>

// Problem constants
#define NNODES 4096
#define KP     64      // paths per node
#define AA     8       // attrs per path
#define DD     128     // embed dim

// ---------------- packed f32x2 helpers (Blackwell FFMA2) ----------------
static __device__ __forceinline__ unsigned long long pack2f(float x) {
    unsigned long long r;
    asm("mov.b64 %0, {%1, %1};" : "=l"(r) : "r"(__float_as_uint(x)));
    return r;
}
static __device__ __forceinline__ unsigned long long ffma2(
    unsigned long long a, unsigned long long b, unsigned long long c) {
    unsigned long long d;
    asm("fma.rn.f32x2 %0, %1, %2, %3;" : "=l"(d) : "l"(a), "l"(b), "l"(c));
    return d;
}
static __device__ __forceinline__ void unpack2f(unsigned long long v, float& lo, float& hi) {
    unsigned int a, b;
    asm("mov.b64 {%0, %1}, %2;" : "=r"(a), "=r"(b) : "l"(v));
    lo = __uint_as_float(a);
    hi = __uint_as_float(b);
}

// ---------------- fused 64xNCxKD GEMM + bias + relu -----------------------
// 256 threads. Thread (tr = tid/16, tc = tid%16) computes rows [4*tr, 4*tr+4)
// x cols [tc*CPT, tc*CPT+CPT). X in smem [64][xstride]; W row-major global
// [KD][NC]; bias NC floats (smem or global); Out smem [64][ostride].
template <int NC, int KD>
static __device__ __forceinline__ void gemm64_relu(
    const float* __restrict__ Xs, int xstride,
    const float* __restrict__ W,
    const float* __restrict__ bias,
    float* __restrict__ Out, int ostride, int tid)
{
    constexpr int CPT = NC / 16;  // cols per thread (16 or 8)
    constexpr int PJ  = CPT / 2;  // f32x2 pairs per thread row
    const int tc = tid & 15, tr = tid >> 4;
    const int c0 = tc * CPT, r0 = tr * 4;

    unsigned long long acc[4][PJ];
#pragma unroll
    for (int i = 0; i < 4; i++)
#pragma unroll
        for (int j = 0; j < PJ; j++) acc[i][j] = 0ull;

    const float* x0 = Xs + r0 * xstride;
#pragma unroll 4
    for (int k = 0; k < KD; k++) {
        unsigned long long xp[4];
#pragma unroll
        for (int i = 0; i < 4; i++) xp[i] = pack2f(x0[i * xstride + k]);
        const unsigned long long* wr =
            (const unsigned long long*)(W + (size_t)k * NC + c0);
#pragma unroll
        for (int j = 0; j < PJ; j++) {
            unsigned long long wv = wr[j];
#pragma unroll
            for (int i = 0; i < 4; i++) acc[i][j] = ffma2(xp[i], wv, acc[i][j]);
        }
    }
#pragma unroll
    for (int i = 0; i < 4; i++) {
        float* orow = Out + (r0 + i) * ostride + c0;
#pragma unroll
        for (int j = 0; j < PJ; j++) {
            float lo, hi;
            unpack2f(acc[i][j], lo, hi);
            lo += bias[c0 + 2 * j];
            hi += bias[c0 + 2 * j + 1];
            orow[2 * j]     = fmaxf(lo, 0.f);
            orow[2 * j + 1] = fmaxf(hi, 0.f);
        }
    }
}

// ---------------- main kernel: one CTA per node ---------------------------
__global__ void __launch_bounds__(256, 1)
l2agg_kernel(const int*   __restrict__ nodes,
             const int*   __restrict__ prel,     // [N][K][2]
             const int*   __restrict__ pnbr,     // [N][K]
             const int*   __restrict__ attrs,    // [N][K][A]
             const float* __restrict__ u2e,      // [NU][128]
             const float* __restrict__ r2e,      // [NR][128]
             const float* __restrict__ ua2e,     // [NA][128]
             const float* __restrict__ W1, const float* __restrict__ b1,
             const float* __restrict__ W2, const float* __restrict__ b2,
             const float* __restrict__ A1, const float* __restrict__ ab1,
             const float* __restrict__ A2, const float* __restrict__ ab2,
             const float* __restrict__ A3, const float* __restrict__ ab3,
             float*       __restrict__ out)      // [N][128]
{
    extern __shared__ float smem[];
    float* xs   = smem;                 // [64][512]; later reused: h2s/a1s/a2s
    float* h1s  = smem + 64 * 512;      // [64][256]
    float* aux  = h1s + 64 * 256;       // sef[128] sp1[128] logits[64] wts[64]
    float* sef    = aux;
    float* sp1    = aux + 128;
    float* logits = aux + 256;
    float* wts    = aux + 320;

    const int n    = blockIdx.x;
    const int tid  = threadIdx.x;
    const int warp = tid >> 5, lane = tid & 31;

    // ---- gather X = [r1 | r2 | nbr | sum(attrs)] into smem, one warp/path
    const float4* r2e4  = (const float4*)r2e;
    const float4* u2e4  = (const float4*)u2e;
    const float4* ua2e4 = (const float4*)ua2e;
#pragma unroll
    for (int it = 0; it < 8; ++it) {
        const int p    = warp * 8 + it;
        const int base = n * KP + p;
        const int i0 = prel[base * 2 + 0];
        const int i1 = prel[base * 2 + 1];
        const int nb = pnbr[base];
        float4 v1 = r2e4[(size_t)i0 * 32 + lane];
        float4 v2 = r2e4[(size_t)i1 * 32 + lane];
        float4 vn = u2e4[(size_t)nb * 32 + lane];
        float4 va = make_float4(0.f, 0.f, 0.f, 0.f);
#pragma unroll
        for (int a = 0; a < AA; a++) {
            const int ia = attrs[base * AA + a];
            float4 t = ua2e4[(size_t)ia * 32 + lane];
            va.x += t.x; va.y += t.y; va.z += t.z; va.w += t.w;
        }
        float4* xrow = (float4*)(xs + p * 512);
        xrow[lane]      = v1;
        xrow[32 + lane] = v2;
        xrow[64 + lane] = vn;
        xrow[96 + lane] = va;
    }
    if (tid < 32) {
        const int sn = nodes[n];
        ((float4*)sef)[tid] = u2e4[(size_t)sn * 32 + tid];
    }
    __syncthreads();

    // ---- layer 1: h1 = relu(x @ W1 + b1)   [64,512]x[512,256]
    gemm64_relu<256, 512>(xs, 512, W1, b1, h1s, 256, tid);
    __syncthreads();

    // ---- layer 2: h2 = relu(h1 @ W2 + b2)  [64,256]x[256,128] (h2 -> xs)
    float* h2s = xs;  // [64][128]
    gemm64_relu<128, 256>(h1s, 256, W2, b2, h2s, 128, tid);
    __syncthreads();

    // ---- attention bias: sp1[j] = ab1[j] + self_e . A1[128: , j]
    if (tid < 128) {
        float s = ab1[tid];
#pragma unroll 4
        for (int d = 0; d < 128; ++d)
            s += sef[d] * A1[(size_t)(128 + d) * 128 + tid];
        sp1[tid] = s;
    }
    __syncthreads();

    // ---- a1 = relu(h2 @ A1[:128] + sp1)
    float* a1s = xs + 64 * 128;
    gemm64_relu<128, 128>(h2s, 128, A1, sp1, a1s, 128, tid);
    __syncthreads();

    // ---- a2 = relu(a1 @ A2 + ab2)
    float* a2s = xs + 2 * 64 * 128;
    gemm64_relu<128, 128>(a1s, 128, A2, ab2, a2s, 128, tid);
    __syncthreads();

    // ---- logits[p] = a2[p] . A3 + ab3  (one warp handles 8 paths)
#pragma unroll
    for (int q = 0; q < 8; ++q) {
        const int p = warp * 8 + q;
        const float* ar = a2s + p * 128;
        float s = ar[lane]       * A3[lane]
                + ar[lane + 32]  * A3[lane + 32]
                + ar[lane + 64]  * A3[lane + 64]
                + ar[lane + 96]  * A3[lane + 96];
#pragma unroll
        for (int o = 16; o > 0; o >>= 1) s += __shfl_xor_sync(0xffffffffu, s, o);
        if (lane == 0) logits[p] = s + ab3[0];
    }
    __syncthreads();

    // ---- softmax over 64 paths (warp 0)
    if (warp == 0) {
        float l0 = logits[lane], l1 = logits[lane + 32];
        float m = fmaxf(l0, l1);
#pragma unroll
        for (int o = 16; o > 0; o >>= 1) m = fmaxf(m, __shfl_xor_sync(0xffffffffu, m, o));
        float e0 = expf(l0 - m), e1 = expf(l1 - m);
        float s = e0 + e1;
#pragma unroll
        for (int o = 16; o > 0; o >>= 1) s += __shfl_xor_sync(0xffffffffu, s, o);
        const float inv = 1.f / s;
        wts[lane]      = e0 * inv;
        wts[lane + 32] = e1 * inv;
    }
    __syncthreads();

    // ---- out[n] = sum_p w[p] * h2[p]
    if (tid < 128) {
        float acc = 0.f;
#pragma unroll 4
        for (int p = 0; p < 64; ++p) acc += wts[p] * h2s[p * 128 + tid];
        out[(size_t)n * 128 + tid] = acc;
    }
}

// ---------------- launch ---------------------------------------------------
extern "C" void kernel_launch(void* const* d_in, const int* in_sizes, int n_in,
                              void* d_out, int out_size)
{
    const int*   nodes = (const int*)  d_in[0];
    const int*   prel  = (const int*)  d_in[1];
    const int*   pnbr  = (const int*)  d_in[2];
    const int*   attrs = (const int*)  d_in[3];
    const float* u2e   = (const float*)d_in[4];
    const float* r2e   = (const float*)d_in[5];
    const float* ua2e  = (const float*)d_in[6];
    const float* W1    = (const float*)d_in[7];
    const float* b1    = (const float*)d_in[8];
    const float* W2    = (const float*)d_in[9];
    const float* b2    = (const float*)d_in[10];
    const float* A1    = (const float*)d_in[11];
    const float* ab1   = (const float*)d_in[12];
    const float* A2    = (const float*)d_in[13];
    const float* ab2   = (const float*)d_in[14];
    const float* A3    = (const float*)d_in[15];
    const float* ab3   = (const float*)d_in[16];
    float* out = (float*)d_out;

    const int smem_bytes = (64 * 512 + 64 * 256 + 384) * (int)sizeof(float); // 198144
    cudaFuncSetAttribute(l2agg_kernel,
                         cudaFuncAttributeMaxDynamicSharedMemorySize, smem_bytes);
    l2agg_kernel<<<NNODES, 256, smem_bytes>>>(
        nodes, prel, pnbr, attrs, u2e, r2e, ua2e,
        W1, b1, W2, b2, A1, ab1, A2, ab2, A3, ab3, out);
}

// round 2
// speedup vs baseline: 3.8914x; 3.8914x over previous
#include <cuda_runtime.h>

// Problem constants
#define NNODES 4096
#define KP     64      // paths per node
#define AA     8       // attrs per path
#define DD     128     // embed dim

// smem layout (floats)
#define XSTRIDE   516                  // X row stride (64 rows)
#define XS_SIZE   (64 * XSTRIDE)       // 33024
#define H1STRIDE  260
#define H2STRIDE  132
#define WBUF_OFF  XS_SIZE              // double buffer: 2 * 8192 floats
#define WCHUNK_F  8192                 // floats per W chunk (32KB)
#define AUX_OFF   (WBUF_OFF + 2 * WCHUNK_F)   // 49408
#define SMEM_F    (AUX_OFF + 384)             // 49792 floats = 199168 B

// ---------------- packed f32x2 helpers (Blackwell FFMA2) ----------------
static __device__ __forceinline__ unsigned long long pack2f(float x) {
    unsigned long long r;
    asm("mov.b64 %0, {%1, %1};" : "=l"(r) : "r"(__float_as_uint(x)));
    return r;
}
static __device__ __forceinline__ unsigned long long ffma2(
    unsigned long long a, unsigned long long b, unsigned long long c) {
    unsigned long long d;
    asm("fma.rn.f32x2 %0, %1, %2, %3;" : "=l"(d) : "l"(a), "l"(b), "l"(c));
    return d;
}
static __device__ __forceinline__ void unpack2f(unsigned long long v, float& lo, float& hi) {
    unsigned int a, b;
    asm("mov.b64 {%0, %1}, %2;" : "=r"(a), "=r"(b) : "l"(v));
    lo = __uint_as_float(a);
    hi = __uint_as_float(b);
}

// ---------------- cp.async helpers ---------------------------------------
static __device__ __forceinline__ void cp_async16(float* smem_dst, const float* gsrc) {
    unsigned int saddr = (unsigned int)__cvta_generic_to_shared(smem_dst);
    asm volatile("cp.async.cg.shared.global [%0], [%1], 16;" :: "r"(saddr), "l"(gsrc));
}
static __device__ __forceinline__ void cp_commit() {
    asm volatile("cp.async.commit_group;");
}
template <int N>
static __device__ __forceinline__ void cp_wait() {
    asm volatile("cp.async.wait_group %0;" :: "n"(N));
}

// ---------------- fused 64xNC GEMM, W staged via cp.async ring ------------
// 256 threads. tc = tid&15 owns column pairs {2*tc + 32*j, j<NC/32};
// tr = tid>>4 owns rows [4*tr, 4*tr+4).  W global row-major [KD][NC],
// staged in 32KB chunks (CK rows) into wbuf (2 * WCHUNK_F floats).
template <int NC, int KD, int CK>
static __device__ __forceinline__ void gemm64_relu(
    const float* __restrict__ Xs, int xst,
    const float* __restrict__ Wg,
    const float* __restrict__ bias,
    float* __restrict__ Out, int ost,
    float* __restrict__ wbuf, int tid)
{
    constexpr int PAIRS  = NC / 32;       // f32x2 pairs per thread (8 or 4)
    constexpr int NCHUNK = KD / CK;
    static_assert(CK * NC == WCHUNK_F, "chunk size mismatch");
    const int tc = tid & 15, tr = tid >> 4;
    const int r0 = tr * 4;

    unsigned long long acc[4][PAIRS];
#pragma unroll
    for (int i = 0; i < 4; i++)
#pragma unroll
        for (int j = 0; j < PAIRS; j++) acc[i][j] = 0ull;

    // prefetch chunk 0
    {
        const float* src = Wg;
        float* dst = wbuf;
#pragma unroll
        for (int t = 0; t < WCHUNK_F / 4 / 256; t++)
            cp_async16(dst + 4 * (tid + 256 * t), src + 4 * (tid + 256 * t));
        cp_commit();
    }

    for (int c = 0; c < NCHUNK; ++c) {
        if (c + 1 < NCHUNK) {
            const float* src = Wg + (size_t)(c + 1) * WCHUNK_F;
            float* dst = wbuf + ((c + 1) & 1) * WCHUNK_F;
#pragma unroll
            for (int t = 0; t < WCHUNK_F / 4 / 256; t++)
                cp_async16(dst + 4 * (tid + 256 * t), src + 4 * (tid + 256 * t));
            cp_commit();
            cp_wait<1>();
        } else {
            cp_wait<0>();
        }
        __syncthreads();   // chunk c visible to all threads

        const float* wb = wbuf + (c & 1) * WCHUNK_F;
        const float* x0 = Xs + r0 * xst + c * CK;
#pragma unroll 2
        for (int kk = 0; kk < CK; kk += 4) {
            float4 xv[4];
#pragma unroll
            for (int i = 0; i < 4; i++)
                xv[i] = *(const float4*)(x0 + i * xst + kk);
#pragma unroll
            for (int u = 0; u < 4; u++) {
                unsigned long long xp[4];
                xp[0] = pack2f(u == 0 ? xv[0].x : u == 1 ? xv[0].y : u == 2 ? xv[0].z : xv[0].w);
                xp[1] = pack2f(u == 0 ? xv[1].x : u == 1 ? xv[1].y : u == 2 ? xv[1].z : xv[1].w);
                xp[2] = pack2f(u == 0 ? xv[2].x : u == 1 ? xv[2].y : u == 2 ? xv[2].z : xv[2].w);
                xp[3] = pack2f(u == 0 ? xv[3].x : u == 1 ? xv[3].y : u == 2 ? xv[3].z : xv[3].w);
                const unsigned long long* wr =
                    (const unsigned long long*)(wb + (kk + u) * NC) + tc;
#pragma unroll
                for (int j = 0; j < PAIRS; j++) {
                    unsigned long long wv = wr[16 * j];
#pragma unroll
                    for (int i = 0; i < 4; i++) acc[i][j] = ffma2(xp[i], wv, acc[i][j]);
                }
            }
        }
        __syncthreads();   // done reading buf before chunk c+2 overwrites it
    }

    // epilogue: bias + relu, cols = 2*tc + 32*j
#pragma unroll
    for (int j = 0; j < PAIRS; j++) {
        const int col = 2 * tc + 32 * j;
        const float blo = bias[col], bhi = bias[col + 1];
#pragma unroll
        for (int i = 0; i < 4; i++) {
            float lo, hi;
            unpack2f(acc[i][j], lo, hi);
            float2 v;
            v.x = fmaxf(lo + blo, 0.f);
            v.y = fmaxf(hi + bhi, 0.f);
            *(float2*)(Out + (r0 + i) * ost + col) = v;
        }
    }
}

// ---------------- main kernel: one CTA per node ---------------------------
__global__ void __launch_bounds__(256, 1)
l2agg_kernel(const int*   __restrict__ nodes,
             const int*   __restrict__ prel,     // [N][K][2]
             const int*   __restrict__ pnbr,     // [N][K]
             const int*   __restrict__ attrs,    // [N][K][A]
             const float* __restrict__ u2e,      // [NU][128]
             const float* __restrict__ r2e,      // [NR][128]
             const float* __restrict__ ua2e,     // [NA][128]
             const float* __restrict__ W1, const float* __restrict__ b1,
             const float* __restrict__ W2, const float* __restrict__ b2,
             const float* __restrict__ A1, const float* __restrict__ ab1,
             const float* __restrict__ A2, const float* __restrict__ ab2,
             const float* __restrict__ A3, const float* __restrict__ ab3,
             float*       __restrict__ out)      // [N][128]
{
    extern __shared__ float smem[];
    float* xs   = smem;                    // X [64][XSTRIDE] during GEMM1
    float* h1s  = smem;                    // h1 [64][260] (after GEMM1)
    float* h2s  = smem + 16896;            // h2 [64][132]
    float* a1s  = smem;                    // a1 [64][132] (h1 dead)
    float* a2s  = smem + 8448;             // a2 [64][132]
    float* wbuf = smem + WBUF_OFF;         // 2 * 8192
    float* aux  = smem + AUX_OFF;
    float* sef    = aux;                   // 128
    float* sp1    = aux + 128;             // 128
    float* logits = aux + 256;             // 64
    float* wts    = aux + 320;             // 64

    const int n    = blockIdx.x;
    const int tid  = threadIdx.x;
    const int warp = tid >> 5, lane = tid & 31;

    // ---- gather X = [r1 | r2 | nbr | sum(attrs)] into smem, one warp/path
    const float4* r2e4  = (const float4*)r2e;
    const float4* u2e4  = (const float4*)u2e;
    const float4* ua2e4 = (const float4*)ua2e;
#pragma unroll
    for (int it = 0; it < 8; ++it) {
        const int p    = warp * 8 + it;
        const int base = n * KP + p;
        const int i0 = prel[base * 2 + 0];
        const int i1 = prel[base * 2 + 1];
        const int nb = pnbr[base];
        float4 v1 = r2e4[(size_t)i0 * 32 + lane];
        float4 v2 = r2e4[(size_t)i1 * 32 + lane];
        float4 vn = u2e4[(size_t)nb * 32 + lane];
        float4 va = make_float4(0.f, 0.f, 0.f, 0.f);
#pragma unroll
        for (int a = 0; a < AA; a++) {
            const int ia = attrs[base * AA + a];
            float4 t = ua2e4[(size_t)ia * 32 + lane];
            va.x += t.x; va.y += t.y; va.z += t.z; va.w += t.w;
        }
        float* xrow = xs + p * XSTRIDE;
        *(float4*)(xrow + 4 * lane)       = v1;
        *(float4*)(xrow + 128 + 4 * lane) = v2;
        *(float4*)(xrow + 256 + 4 * lane) = vn;
        *(float4*)(xrow + 384 + 4 * lane) = va;
    }
    if (tid < 32) {
        const int sn = nodes[n];
        *(float4*)(sef + 4 * tid) = u2e4[(size_t)sn * 32 + tid];
    }
    __syncthreads();

    // ---- layer 1: h1 = relu(x @ W1 + b1)   [64,512]x[512,256] -> regs
    // output written over X region after an extra barrier inside helper
    {
        // compute into registers, then write h1 over xs after a sync
        constexpr int NC = 256, KD = 512, CK = 32;
        constexpr int PAIRS = NC / 32;
        const int tc = tid & 15, tr = tid >> 4;
        const int r0 = tr * 4;
        unsigned long long acc[4][PAIRS];
#pragma unroll
        for (int i = 0; i < 4; i++)
#pragma unroll
            for (int j = 0; j < PAIRS; j++) acc[i][j] = 0ull;

        {
            const float* src = W1;
            float* dst = wbuf;
#pragma unroll
            for (int t = 0; t < WCHUNK_F / 4 / 256; t++)
                cp_async16(dst + 4 * (tid + 256 * t), src + 4 * (tid + 256 * t));
            cp_commit();
        }
        for (int c = 0; c < KD / CK; ++c) {
            if (c + 1 < KD / CK) {
                const float* src = W1 + (size_t)(c + 1) * WCHUNK_F;
                float* dst = wbuf + ((c + 1) & 1) * WCHUNK_F;
#pragma unroll
                for (int t = 0; t < WCHUNK_F / 4 / 256; t++)
                    cp_async16(dst + 4 * (tid + 256 * t), src + 4 * (tid + 256 * t));
                cp_commit();
                cp_wait<1>();
            } else {
                cp_wait<0>();
            }
            __syncthreads();
            const float* wb = wbuf + (c & 1) * WCHUNK_F;
            const float* x0 = xs + r0 * XSTRIDE + c * CK;
#pragma unroll 2
            for (int kk = 0; kk < CK; kk += 4) {
                float4 xv[4];
#pragma unroll
                for (int i = 0; i < 4; i++)
                    xv[i] = *(const float4*)(x0 + i * XSTRIDE + kk);
#pragma unroll
                for (int u = 0; u < 4; u++) {
                    unsigned long long xp[4];
                    xp[0] = pack2f(u == 0 ? xv[0].x : u == 1 ? xv[0].y : u == 2 ? xv[0].z : xv[0].w);
                    xp[1] = pack2f(u == 0 ? xv[1].x : u == 1 ? xv[1].y : u == 2 ? xv[1].z : xv[1].w);
                    xp[2] = pack2f(u == 0 ? xv[2].x : u == 1 ? xv[2].y : u == 2 ? xv[2].z : xv[2].w);
                    xp[3] = pack2f(u == 0 ? xv[3].x : u == 1 ? xv[3].y : u == 2 ? xv[3].z : xv[3].w);
                    const unsigned long long* wr =
                        (const unsigned long long*)(wb + (kk + u) * NC) + tc;
#pragma unroll
                    for (int j = 0; j < PAIRS; j++) {
                        unsigned long long wv = wr[16 * j];
#pragma unroll
                        for (int i = 0; i < 4; i++) acc[i][j] = ffma2(xp[i], wv, acc[i][j]);
                    }
                }
            }
            __syncthreads();
        }
        // all threads done reading X -> safe to overwrite with h1
        __syncthreads();
#pragma unroll
        for (int j = 0; j < PAIRS; j++) {
            const int col = 2 * tc + 32 * j;
            const float blo = b1[col], bhi = b1[col + 1];
#pragma unroll
            for (int i = 0; i < 4; i++) {
                float lo, hi;
                unpack2f(acc[i][j], lo, hi);
                float2 v;
                v.x = fmaxf(lo + blo, 0.f);
                v.y = fmaxf(hi + bhi, 0.f);
                *(float2*)(h1s + (r0 + i) * H1STRIDE + col) = v;
            }
        }
    }
    __syncthreads();

    // ---- layer 2: h2 = relu(h1 @ W2 + b2)  [64,256]x[256,128]
    gemm64_relu<128, 256, 64>(h1s, H1STRIDE, W2, b2, h2s, H2STRIDE, wbuf, tid);
    __syncthreads();

    // ---- attention bias: sp1[j] = ab1[j] + self_e . A1[128: , j]
    if (tid < 128) {
        float s = ab1[tid];
#pragma unroll 4
        for (int d = 0; d < 128; ++d)
            s += sef[d] * A1[(size_t)(128 + d) * 128 + tid];
        sp1[tid] = s;
    }
    __syncthreads();

    // ---- a1 = relu(h2 @ A1[:128] + sp1)
    gemm64_relu<128, 128, 64>(h2s, H2STRIDE, A1, sp1, a1s, H2STRIDE, wbuf, tid);
    __syncthreads();

    // ---- a2 = relu(a1 @ A2 + ab2)
    gemm64_relu<128, 128, 64>(a1s, H2STRIDE, A2, ab2, a2s, H2STRIDE, wbuf, tid);
    __syncthreads();

    // ---- logits[p] = a2[p] . A3 + ab3  (one warp handles 8 paths)
#pragma unroll
    for (int q = 0; q < 8; ++q) {
        const int p = warp * 8 + q;
        const float* ar = a2s + p * H2STRIDE;
        float s = ar[lane]       * A3[lane]
                + ar[lane + 32]  * A3[lane + 32]
                + ar[lane + 64]  * A3[lane + 64]
                + ar[lane + 96]  * A3[lane + 96];
#pragma unroll
        for (int o = 16; o > 0; o >>= 1) s += __shfl_xor_sync(0xffffffffu, s, o);
        if (lane == 0) logits[p] = s + ab3[0];
    }
    __syncthreads();

    // ---- softmax over 64 paths (warp 0)
    if (warp == 0) {
        float l0 = logits[lane], l1 = logits[lane + 32];
        float m = fmaxf(l0, l1);
#pragma unroll
        for (int o = 16; o > 0; o >>= 1) m = fmaxf(m, __shfl_xor_sync(0xffffffffu, m, o));
        float e0 = expf(l0 - m), e1 = expf(l1 - m);
        float s = e0 + e1;
#pragma unroll
        for (int o = 16; o > 0; o >>= 1) s += __shfl_xor_sync(0xffffffffu, s, o);
        const float inv = 1.f / s;
        wts[lane]      = e0 * inv;
        wts[lane + 32] = e1 * inv;
    }
    __syncthreads();

    // ---- out[n] = sum_p w[p] * h2[p]
    if (tid < 128) {
        float acc = 0.f;
#pragma unroll 4
        for (int p = 0; p < 64; ++p) acc += wts[p] * h2s[p * H2STRIDE + tid];
        out[(size_t)n * 128 + tid] = acc;
    }
}

// ---------------- launch ---------------------------------------------------
extern "C" void kernel_launch(void* const* d_in, const int* in_sizes, int n_in,
                              void* d_out, int out_size)
{
    const int*   nodes = (const int*)  d_in[0];
    const int*   prel  = (const int*)  d_in[1];
    const int*   pnbr  = (const int*)  d_in[2];
    const int*   attrs = (const int*)  d_in[3];
    const float* u2e   = (const float*)d_in[4];
    const float* r2e   = (const float*)d_in[5];
    const float* ua2e  = (const float*)d_in[6];
    const float* W1    = (const float*)d_in[7];
    const float* b1    = (const float*)d_in[8];
    const float* W2    = (const float*)d_in[9];
    const float* b2    = (const float*)d_in[10];
    const float* A1    = (const float*)d_in[11];
    const float* ab1   = (const float*)d_in[12];
    const float* A2    = (const float*)d_in[13];
    const float* ab2   = (const float*)d_in[14];
    const float* A3    = (const float*)d_in[15];
    const float* ab3   = (const float*)d_in[16];
    float* out = (float*)d_out;

    const int smem_bytes = SMEM_F * (int)sizeof(float);   // 199168 B
    cudaFuncSetAttribute(l2agg_kernel,
                         cudaFuncAttributeMaxDynamicSharedMemorySize, smem_bytes);
    l2agg_kernel<<<NNODES, 256, smem_bytes>>>(
        nodes, prel, pnbr, attrs, u2e, r2e, ua2e,
        W1, b1, W2, b2, A1, ab1, A2, ab2, A3, ab3, out);
}